// round 6
// baseline (speedup 1.0000x reference)
#include <cuda_runtime.h>
#include <cuda_bf16.h>
#include <math.h>
#include <stdint.h>

// TreeLSTM — round 6: TF32 HMMA, warp tile 64x64 (4 warps, 128 thr, CTA 128x128),
// 3-stage cp.async pipeline. LDS-traffic-per-FLOP cut 33% vs round 5.

#define D    256
#define D3   768
#define MAX_P 100000

// ---------------- scratch ----------------
__device__ float g_fc[(size_t)MAX_P * D];
__device__ float g_iact[(size_t)MAX_P * D];
__device__ float g_gact[(size_t)MAX_P * D];
__device__ float g_hs_sum[(size_t)MAX_P * D];
__device__ float g_wf_t[D * D];     // tf32-rounded, [N][K]
__device__ float g_wg_t[D3 * D];    // tf32-rounded, [N][K]

// ---------------- helpers ----------------
__device__ __forceinline__ uint32_t smem_to_u32(const void* p) {
    uint32_t a;
    asm("{ .reg .u64 t; cvta.to.shared.u64 t, %1; cvt.u32.u64 %0, t; }" : "=r"(a) : "l"(p));
    return a;
}
__device__ __forceinline__ float sigmoid_f(float x) { return 1.0f / (1.0f + __expf(-x)); }
__device__ __forceinline__ float tf32_round(float x) {
    uint32_t r;
    asm("cvt.rna.tf32.f32 %0, %1;" : "=r"(r) : "f"(x));
    return __uint_as_float(r);
}
__device__ __forceinline__ uint32_t tf32_u(uint32_t x) {
    uint32_t r;
    asm("cvt.rna.tf32.f32 %0, %1;" : "=r"(r) : "f"(__uint_as_float(x)));
    return r;
}

#define CP_ASYNC16(dst, src) \
    asm volatile("cp.async.cg.shared.global [%0], [%1], 16;" :: "r"(dst), "l"(src))
#define CP_COMMIT() asm volatile("cp.async.commit_group;")
#define CP_WAIT_1() asm volatile("cp.async.wait_group 1;")

__device__ __forceinline__ void ldsm_x4(uint32_t a[4], uint32_t addr) {
    asm volatile("ldmatrix.sync.aligned.m8n8.x4.shared.b16 {%0,%1,%2,%3}, [%4];"
        : "=r"(a[0]), "=r"(a[1]), "=r"(a[2]), "=r"(a[3]) : "r"(addr));
}
__device__ __forceinline__ void mma_tf32(float c[4], const uint32_t a[4], const uint32_t b[2]) {
    asm volatile(
        "mma.sync.aligned.m16n8k8.row.col.f32.tf32.tf32.f32 "
        "{%0,%1,%2,%3}, {%4,%5,%6,%7}, {%8,%9}, {%0,%1,%2,%3};"
        : "+f"(c[0]), "+f"(c[1]), "+f"(c[2]), "+f"(c[3])
        : "r"(a[0]), "r"(a[1]), "r"(a[2]), "r"(a[3]), "r"(b[0]), "r"(b[1]));
}

// Swizzled byte offset in a [rows][32 f32] tile: 128B rows, 8 chunks of 16B.
__device__ __forceinline__ uint32_t swz8(int row, int ch) {
    return (uint32_t)(row * 128 + (((ch) ^ ((row) & 7)) << 4));
}

// ---------------------------------------------------------------------------
// k_wsplit: W[256 x ncols] -> T [ncols][256] fp32 (tf32-rounded), transposed
// ---------------------------------------------------------------------------
__global__ void k_wsplit(const float* __restrict__ W, int ncols,
                         float* __restrict__ T) {
    __shared__ float s[32][33];
    int nt = blockIdx.x * 32, kt = blockIdx.y * 32;
    int tx = threadIdx.x & 31, ty = threadIdx.x >> 5;
    #pragma unroll
    for (int i = 0; i < 4; ++i)
        s[ty + i * 8][tx] = W[(size_t)(kt + ty + i * 8) * ncols + nt + tx];
    __syncthreads();
    #pragma unroll
    for (int i = 0; i < 4; ++i) {
        int n = nt + ty + i * 8;
        int k = kt + tx;
        T[(size_t)n * D + k] = tf32_round(s[tx][ty + i * 8]);
    }
}

// ---------------------------------------------------------------------------
// k_hs_sum: per-parent segment sum of child_hs
// ---------------------------------------------------------------------------
__global__ void k_hs_sum(const float* __restrict__ hs, const int* __restrict__ seg,
                         int E, float* __restrict__ out) {
    __shared__ int sb2[2];
    int p = blockIdx.x;
    if (threadIdx.x < 2) {
        int target = p + (int)threadIdx.x;
        int lo = 0, hi = E;
        while (lo < hi) { int m = (lo + hi) >> 1; if (seg[m] < target) lo = m + 1; else hi = m; }
        sb2[threadIdx.x] = lo;
    }
    __syncthreads();
    int lo = sb2[0], hi = sb2[1];
    float s = 0.0f;
    for (int e = lo; e < hi; ++e) s += hs[(size_t)e * D + threadIdx.x];
    out[(size_t)p * D + threadIdx.x] = s;
}

// ---------------------------------------------------------------------------
// k_gemm<MODE>: TF32 GEMM, CTA 128x128, 4 warps (2x2), warp tile 64x64,
// BK=32 x 8 chunks, 3-stage cp.async.
// blockIdx.x: MODE0 -> nhalf (0..1); MODE1 -> gate*2 + nhalf (0..5).
// MODE 0: atomicAdd fc[seg[row]] += sigmoid(v + b) * cc[row].
// MODE 1: per-gate activation stores (sig/sig/tanh).
// ---------------------------------------------------------------------------
#define SM_A 0
#define SM_B 16384
#define SM_STAGE 32768
#define SM_TOTAL (3 * SM_STAGE)

template <int MODE>
__global__ void __launch_bounds__(128, 2)
k_gemm(const float* __restrict__ A32,
       const float* __restrict__ Bt_g,
       const float* __restrict__ bias_g,
       const float* __restrict__ cc,
       const int* __restrict__ seg,
       float* __restrict__ fc,
       float* __restrict__ o0, float* __restrict__ o1, float* __restrict__ o2,
       int Mtot) {
    extern __shared__ char smem[];
    const uint32_t sb = smem_to_u32(smem);
    const int tid  = threadIdx.x;
    const int lane = tid & 31;
    const int wid  = tid >> 5;
    const int wm   = wid >> 1;          // 0..1
    const int wn   = wid & 1;           // 0..1
    const int bm   = blockIdx.y * 128;
    const int gate  = (MODE == 1) ? ((int)blockIdx.x >> 1) : 0;
    const int nhalf = (MODE == 1) ? ((int)blockIdx.x & 1) : (int)blockIdx.x;

    const float* Bt = Bt_g + ((size_t)gate * 256 + nhalf * 128) * D;
    const float* bias = bias_g + gate * 256 + nhalf * 128;

    float acc[4][8][4];
    #pragma unroll
    for (int i = 0; i < 4; ++i)
        #pragma unroll
        for (int j = 0; j < 8; ++j)
            #pragma unroll
            for (int q = 0; q < 4; ++q) acc[i][j][q] = 0.f;

    // staging: A,B each 128 rows x 8 chunks (16B); 128 thr -> 8 iters per array
    const int srow = tid >> 3;          // 0..15 (+16*it)
    const int sch  = tid & 7;

#define STAGE_AB(kc, slot) do { \
        _Pragma("unroll") \
        for (int _it = 0; _it < 8; ++_it) { \
            int _r = srow + _it * 16; \
            int _ar = min(bm + _r, Mtot - 1); \
            uint32_t _o = swz8(_r, sch); \
            CP_ASYNC16(sb + (slot) + SM_A + _o, A32 + (size_t)_ar * D + (kc) * 32 + sch * 4); \
            CP_ASYNC16(sb + (slot) + SM_B + _o, Bt  + (size_t)_r  * D + (kc) * 32 + sch * 4); \
        } \
    } while (0)

    STAGE_AB(0, 0);
    CP_COMMIT();
    STAGE_AB(1, SM_STAGE);
    CP_COMMIT();

    const int l7 = lane & 7;
    const int l8 = (lane >> 3) & 1;
    const int l16 = lane >> 4;

    uint32_t slot = 0;
    #pragma unroll 1
    for (int kc = 0; kc < 8; ++kc) {
        CP_WAIT_1();
        __syncthreads();
        if (kc + 2 < 8) {
            uint32_t ns = (uint32_t)(((kc + 2) % 3) * SM_STAGE);
            STAGE_AB(kc + 2, ns);
        }
        CP_COMMIT();

        const uint32_t base = sb + slot;
        uint32_t ah[4][4], bb[8][4];
        #pragma unroll
        for (int s16 = 0; s16 < 2; ++s16) {
            // B frags: one x4 per n8 tile covers k16
            #pragma unroll
            for (int nf = 0; nf < 8; ++nf) {
                int r = wn * 64 + nf * 8 + l7;
                int ch = 4 * s16 + (lane >> 3);
                ldsm_x4(bb[nf], base + SM_B + swz8(r, ch));
            }
            #pragma unroll
            for (int h = 0; h < 2; ++h) {
                int kk = 2 * s16 + h;
                #pragma unroll
                for (int mf = 0; mf < 4; ++mf) {
                    int r = wm * 64 + mf * 16 + l8 * 8 + l7;
                    int ch = 2 * kk + l16;
                    ldsm_x4(ah[mf], base + SM_A + swz8(r, ch));
                    ah[mf][0] = tf32_u(ah[mf][0]);
                    ah[mf][1] = tf32_u(ah[mf][1]);
                    ah[mf][2] = tf32_u(ah[mf][2]);
                    ah[mf][3] = tf32_u(ah[mf][3]);
                }
                #pragma unroll
                for (int mf = 0; mf < 4; ++mf)
                    #pragma unroll
                    for (int nf = 0; nf < 8; ++nf)
                        mma_tf32(acc[mf][nf], ah[mf], &bb[nf][2 * h]);
            }
        }
        slot = (slot == 2u * SM_STAGE) ? 0u : slot + SM_STAGE;
    }

    // epilogue
    float2 bias2[8];
    #pragma unroll
    for (int nf = 0; nf < 8; ++nf)
        bias2[nf] = *(const float2*)(bias + wn * 64 + nf * 8 + 2 * (lane & 3));

    #pragma unroll
    for (int mf = 0; mf < 4; ++mf) {
        #pragma unroll
        for (int half = 0; half < 2; ++half) {
            int r = bm + wm * 64 + mf * 16 + (lane >> 2) + half * 8;
            bool ok = r < Mtot;
            int sid = (MODE == 0 && ok) ? seg[r] : 0;
            #pragma unroll
            for (int nf = 0; nf < 8; ++nf) {
                int cn = nhalf * 128 + wn * 64 + nf * 8 + 2 * (lane & 3);
                float v0 = acc[mf][nf][half * 2 + 0] + bias2[nf].x;
                float v1 = acc[mf][nf][half * 2 + 1] + bias2[nf].y;
                if (!ok) continue;
                size_t o = (size_t)r * D + cn;
                if (MODE == 0) {
                    float2 ccv = *(const float2*)(cc + o);
                    float* dst = fc + (size_t)sid * D + cn;
                    atomicAdd(dst,     sigmoid_f(v0) * ccv.x);
                    atomicAdd(dst + 1, sigmoid_f(v1) * ccv.y);
                } else {
                    float r0, r1;
                    if (gate == 2) { r0 = tanhf(v0); r1 = tanhf(v1); }
                    else           { r0 = sigmoid_f(v0); r1 = sigmoid_f(v1); }
                    float* op = (gate == 0) ? o0 : (gate == 1) ? o1 : o2;
                    *(float2*)(op + o) = make_float2(r0, r1);
                }
            }
        }
    }
#undef STAGE_AB
}

// ---------------------------------------------------------------------------
// k_final: c = i*g + fc; h = o*tanh(c)
// ---------------------------------------------------------------------------
__global__ void k_final(const float* __restrict__ fc, const float* __restrict__ gi,
                        const float* __restrict__ gg, float* __restrict__ out,
                        int total) {
    int i4 = blockIdx.x * blockDim.x + threadIdx.x;
    if (i4 * 4 < total) {
        size_t idx = (size_t)i4 * 4;
        float4 vi = *(const float4*)(gi + idx);
        float4 vg = *(const float4*)(gg + idx);
        float4 vf = *(const float4*)(fc + idx);
        float4 vo = *(const float4*)(out + idx);
        float4 c = make_float4(vi.x * vg.x + vf.x, vi.y * vg.y + vf.y,
                               vi.z * vg.z + vf.z, vi.w * vg.w + vf.w);
        float4 h = make_float4(vo.x * tanhf(c.x), vo.y * tanhf(c.y),
                               vo.z * tanhf(c.z), vo.w * tanhf(c.w));
        *(float4*)(out + (size_t)total + idx) = c;
        *(float4*)(out + idx) = h;
    }
}

// ---------------------------------------------------------------------------
extern "C" void kernel_launch(void* const* d_in, const int* in_sizes, int n_in,
                              void* d_out, int out_size) {
    const float* child_hs = (const float*)d_in[0];
    const float* child_cs = (const float*)d_in[1];
    const int*   seg      = (const int*)d_in[2];
    const float* Wg = (const float*)d_in[4];
    const float* bg = (const float*)d_in[5];
    const float* Wf = (const float*)d_in[6];
    const float* bf = (const float*)d_in[7];
    (void)n_in;

    int E = in_sizes[2];
    int P = out_size / (2 * D);
    if (P > MAX_P) P = MAX_P;

    float* out = (float*)d_out;

    static bool inited = false;
    static float *fc_p, *ia_p, *ga_p, *hs_p, *wf_p, *wg_p;
    if (!inited) {
        cudaGetSymbolAddress((void**)&fc_p, g_fc);
        cudaGetSymbolAddress((void**)&ia_p, g_iact);
        cudaGetSymbolAddress((void**)&ga_p, g_gact);
        cudaGetSymbolAddress((void**)&hs_p, g_hs_sum);
        cudaGetSymbolAddress((void**)&wf_p, g_wf_t);
        cudaGetSymbolAddress((void**)&wg_p, g_wg_t);
        cudaFuncSetAttribute(k_gemm<0>, cudaFuncAttributeMaxDynamicSharedMemorySize, SM_TOTAL);
        cudaFuncSetAttribute(k_gemm<1>, cudaFuncAttributeMaxDynamicSharedMemorySize, SM_TOTAL);
        inited = true;
    }

    // weight transpose + tf32 rounding
    k_wsplit<<<dim3(D / 32, D / 32), 256>>>(Wf, D, wf_p);
    k_wsplit<<<dim3(D3 / 32, D / 32), 256>>>(Wg, D3, wg_p);

    // zero fc accumulator
    cudaMemsetAsync(fc_p, 0, (size_t)P * D * sizeof(float), 0);

    // segment sum of child_hs
    k_hs_sum<<<P, 256>>>(child_hs, seg, E, hs_p);

    // fGEMM: fc[seg[e]] += sigmoid(hs@Wf^T + bf) * cs
    k_gemm<0><<<dim3(2, (E + 127) / 128), 128, SM_TOTAL>>>(
        child_hs, wf_p, bf, child_cs, seg, fc_p,
        nullptr, nullptr, nullptr, E);

    // gates GEMM: gate 0 -> sig(i), 1 -> sig(o) into out_h, 2 -> tanh(g)
    k_gemm<1><<<dim3(6, (P + 127) / 128), 128, SM_TOTAL>>>(
        hs_p, wg_p, bg, nullptr, nullptr, nullptr,
        ia_p, out, ga_p, P);

    // final elementwise combine
    k_final<<<(P * D / 4 + 255) / 256, 256>>>(fc_p, ia_p, ga_p, out, P * D);
}

// round 7
// speedup vs baseline: 1.3640x; 1.3640x over previous
#include <cuda_runtime.h>
#include <cuda_bf16.h>
#include <math.h>
#include <stdint.h>

// TreeLSTM — round 7: R5 config (CTA 128x128, 8 warps 2x4, warp 64x32, BK32,
// 3-stage cp.async) + A-fragment double buffering + no cvt on A frags.

#define D    256
#define D3   768
#define MAX_P 100000

// ---------------- scratch ----------------
__device__ float g_fc[(size_t)MAX_P * D];
__device__ float g_iact[(size_t)MAX_P * D];
__device__ float g_gact[(size_t)MAX_P * D];
__device__ float g_hs_sum[(size_t)MAX_P * D];
__device__ float g_wf_t[D * D];     // tf32-rounded, [N][K]
__device__ float g_wg_t[D3 * D];    // tf32-rounded, [N][K]

// ---------------- helpers ----------------
__device__ __forceinline__ uint32_t smem_to_u32(const void* p) {
    uint32_t a;
    asm("{ .reg .u64 t; cvta.to.shared.u64 t, %1; cvt.u32.u64 %0, t; }" : "=r"(a) : "l"(p));
    return a;
}
__device__ __forceinline__ float sigmoid_f(float x) { return 1.0f / (1.0f + __expf(-x)); }
__device__ __forceinline__ float tf32_round(float x) {
    uint32_t r;
    asm("cvt.rna.tf32.f32 %0, %1;" : "=r"(r) : "f"(x));
    return __uint_as_float(r);
}

#define CP_ASYNC16(dst, src) \
    asm volatile("cp.async.cg.shared.global [%0], [%1], 16;" :: "r"(dst), "l"(src))
#define CP_COMMIT() asm volatile("cp.async.commit_group;")
#define CP_WAIT_1() asm volatile("cp.async.wait_group 1;")

__device__ __forceinline__ void ldsm_x4(uint32_t a[4], uint32_t addr) {
    asm volatile("ldmatrix.sync.aligned.m8n8.x4.shared.b16 {%0,%1,%2,%3}, [%4];"
        : "=r"(a[0]), "=r"(a[1]), "=r"(a[2]), "=r"(a[3]) : "r"(addr));
}
__device__ __forceinline__ void mma_tf32(float c[4], const uint32_t a[4], const uint32_t b[2]) {
    asm volatile(
        "mma.sync.aligned.m16n8k8.row.col.f32.tf32.tf32.f32 "
        "{%0,%1,%2,%3}, {%4,%5,%6,%7}, {%8,%9}, {%0,%1,%2,%3};"
        : "+f"(c[0]), "+f"(c[1]), "+f"(c[2]), "+f"(c[3])
        : "r"(a[0]), "r"(a[1]), "r"(a[2]), "r"(a[3]), "r"(b[0]), "r"(b[1]));
}

// Swizzled byte offset in a [rows][32 f32] tile: 128B rows, 8 chunks of 16B.
__device__ __forceinline__ uint32_t swz8(int row, int ch) {
    return (uint32_t)(row * 128 + (((ch) ^ ((row) & 7)) << 4));
}

// ---------------------------------------------------------------------------
// k_wsplit: W[256 x ncols] -> T [ncols][256] fp32 (tf32-rounded), transposed
// ---------------------------------------------------------------------------
__global__ void k_wsplit(const float* __restrict__ W, int ncols,
                         float* __restrict__ T) {
    __shared__ float s[32][33];
    int nt = blockIdx.x * 32, kt = blockIdx.y * 32;
    int tx = threadIdx.x & 31, ty = threadIdx.x >> 5;
    #pragma unroll
    for (int i = 0; i < 4; ++i)
        s[ty + i * 8][tx] = W[(size_t)(kt + ty + i * 8) * ncols + nt + tx];
    __syncthreads();
    #pragma unroll
    for (int i = 0; i < 4; ++i) {
        int n = nt + ty + i * 8;
        int k = kt + tx;
        T[(size_t)n * D + k] = tf32_round(s[tx][ty + i * 8]);
    }
}

// ---------------------------------------------------------------------------
// k_hs_sum: per-parent segment sum of child_hs
// ---------------------------------------------------------------------------
__global__ void k_hs_sum(const float* __restrict__ hs, const int* __restrict__ seg,
                         int E, float* __restrict__ out) {
    __shared__ int sb2[2];
    int p = blockIdx.x;
    if (threadIdx.x < 2) {
        int target = p + (int)threadIdx.x;
        int lo = 0, hi = E;
        while (lo < hi) { int m = (lo + hi) >> 1; if (seg[m] < target) lo = m + 1; else hi = m; }
        sb2[threadIdx.x] = lo;
    }
    __syncthreads();
    int lo = sb2[0], hi = sb2[1];
    float s = 0.0f;
    for (int e = lo; e < hi; ++e) s += hs[(size_t)e * D + threadIdx.x];
    out[(size_t)p * D + threadIdx.x] = s;
}

// ---------------------------------------------------------------------------
// k_gemm<MODE>: TF32 GEMM. CTA 128x128, 8 warps (2m x 4n), warp tile 64x32,
// BK=32 x 8 chunks, 3-stage cp.async, A-fragment double buffering.
// blockIdx.x: MODE0 -> nhalf (0..1); MODE1 -> gate*2 + nhalf (0..5).
// MODE 0: atomicAdd fc[seg[row]] += sigmoid(v + b) * cc[row].
// MODE 1: per-gate activation stores (sig/sig/tanh).
// ---------------------------------------------------------------------------
#define SM_A 0
#define SM_B 16384
#define SM_STAGE 32768
#define SM_TOTAL (3 * SM_STAGE)

template <int MODE>
__global__ void __launch_bounds__(256, 2)
k_gemm(const float* __restrict__ A32,
       const float* __restrict__ Bt_g,
       const float* __restrict__ bias_g,
       const float* __restrict__ cc,
       const int* __restrict__ seg,
       float* __restrict__ fc,
       float* __restrict__ o0, float* __restrict__ o1, float* __restrict__ o2,
       int Mtot) {
    extern __shared__ char smem[];
    const uint32_t sb = smem_to_u32(smem);
    const int tid  = threadIdx.x;
    const int lane = tid & 31;
    const int wid  = tid >> 5;
    const int wm   = wid >> 2;          // 0..1
    const int wn   = wid & 3;           // 0..3
    const int bm   = blockIdx.y * 128;
    const int gate  = (MODE == 1) ? ((int)blockIdx.x >> 1) : 0;
    const int nhalf = (MODE == 1) ? ((int)blockIdx.x & 1) : (int)blockIdx.x;

    const float* Bt = Bt_g + ((size_t)gate * 256 + nhalf * 128) * D;
    const float* bias = bias_g + gate * 256 + nhalf * 128;

    float acc[4][4][4];
    #pragma unroll
    for (int i = 0; i < 4; ++i)
        #pragma unroll
        for (int j = 0; j < 4; ++j)
            #pragma unroll
            for (int q = 0; q < 4; ++q) acc[i][j][q] = 0.f;

    // staging: A,B each 128 rows x 8 chunks (16B); 256 thr -> 4 iters
    const int srow = tid >> 3;          // 0..31 (+32*it)
    const int sch  = tid & 7;

#define STAGE_AB(kc, slot) do { \
        _Pragma("unroll") \
        for (int _it = 0; _it < 4; ++_it) { \
            int _r = srow + _it * 32; \
            int _ar = min(bm + _r, Mtot - 1); \
            uint32_t _o = swz8(_r, sch); \
            CP_ASYNC16(sb + (slot) + SM_A + _o, A32 + (size_t)_ar * D + (kc) * 32 + sch * 4); \
            CP_ASYNC16(sb + (slot) + SM_B + _o, Bt  + (size_t)_r  * D + (kc) * 32 + sch * 4); \
        } \
    } while (0)

    STAGE_AB(0, 0);
    CP_COMMIT();
    STAGE_AB(1, SM_STAGE);
    CP_COMMIT();

    const int l7 = lane & 7;
    const int l8 = (lane >> 3) & 1;
    const int l16 = lane >> 4;

    // fragment addresses (swizzle depends on row & chunk; rows fixed per warp)
    const int arow_f = wm * 64 + l8 * 8 + l7;   // + mf*16, chunk = 2*kk + l16

    uint32_t slot = 0;
    #pragma unroll 1
    for (int kc = 0; kc < 8; ++kc) {
        CP_WAIT_1();
        __syncthreads();
        if (kc + 2 < 8) {
            uint32_t ns = (uint32_t)(((kc + 2) % 3) * SM_STAGE);
            STAGE_AB(kc + 2, ns);
        }
        CP_COMMIT();

        const uint32_t base = sb + slot;
        uint32_t ah[2][4][4];   // double-buffered A frags [buf][mf][4]
        uint32_t bb[4][4];      // B frags for current k16 [nf][4]

        // preload A frags for kk=0
        #pragma unroll
        for (int mf = 0; mf < 4; ++mf)
            ldsm_x4(ah[0][mf], base + SM_A + swz8(arow_f + mf * 16, l16));

        #pragma unroll
        for (int s16 = 0; s16 < 2; ++s16) {
            // B frags for this k16 (4 ldsm x4, covers n32 x k16)
            #pragma unroll
            for (int nf = 0; nf < 4; ++nf) {
                int r = wn * 32 + nf * 8 + l7;
                int ch = 4 * s16 + (lane >> 3);
                ldsm_x4(bb[nf], base + SM_B + swz8(r, ch));
            }
            #pragma unroll
            for (int h = 0; h < 2; ++h) {
                int kk = 2 * s16 + h;           // 0..3
                int cur = kk & 1;
                // prefetch next kk's A frags before issuing MMAs
                if (kk < 3) {
                    int nch = 2 * (kk + 1) + l16;
                    #pragma unroll
                    for (int mf = 0; mf < 4; ++mf)
                        ldsm_x4(ah[cur ^ 1][mf], base + SM_A + swz8(arow_f + mf * 16, nch));
                }
                #pragma unroll
                for (int mf = 0; mf < 4; ++mf)
                    #pragma unroll
                    for (int nf = 0; nf < 4; ++nf)
                        mma_tf32(acc[mf][nf], ah[cur][mf], &bb[nf][2 * h]);
            }
        }
        slot = (slot == 2u * SM_STAGE) ? 0u : slot + SM_STAGE;
    }

    // epilogue
    float2 bias2[4];
    #pragma unroll
    for (int nf = 0; nf < 4; ++nf)
        bias2[nf] = *(const float2*)(bias + wn * 32 + nf * 8 + 2 * (lane & 3));

    #pragma unroll
    for (int mf = 0; mf < 4; ++mf) {
        #pragma unroll
        for (int half = 0; half < 2; ++half) {
            int r = bm + wm * 64 + mf * 16 + (lane >> 2) + half * 8;
            bool ok = r < Mtot;
            int sid = (MODE == 0 && ok) ? seg[r] : 0;
            #pragma unroll
            for (int nf = 0; nf < 4; ++nf) {
                int cn = nhalf * 128 + wn * 32 + nf * 8 + 2 * (lane & 3);
                float v0 = acc[mf][nf][half * 2 + 0] + bias2[nf].x;
                float v1 = acc[mf][nf][half * 2 + 1] + bias2[nf].y;
                if (!ok) continue;
                size_t o = (size_t)r * D + cn;
                if (MODE == 0) {
                    float2 ccv = *(const float2*)(cc + o);
                    float* dst = fc + (size_t)sid * D + cn;
                    atomicAdd(dst,     sigmoid_f(v0) * ccv.x);
                    atomicAdd(dst + 1, sigmoid_f(v1) * ccv.y);
                } else {
                    float r0, r1;
                    if (gate == 2) { r0 = tanhf(v0); r1 = tanhf(v1); }
                    else           { r0 = sigmoid_f(v0); r1 = sigmoid_f(v1); }
                    float* op = (gate == 0) ? o0 : (gate == 1) ? o1 : o2;
                    *(float2*)(op + o) = make_float2(r0, r1);
                }
            }
        }
    }
#undef STAGE_AB
}

// ---------------------------------------------------------------------------
// k_final: c = i*g + fc; h = o*tanh(c)
// ---------------------------------------------------------------------------
__global__ void k_final(const float* __restrict__ fc, const float* __restrict__ gi,
                        const float* __restrict__ gg, float* __restrict__ out,
                        int total) {
    int i4 = blockIdx.x * blockDim.x + threadIdx.x;
    if (i4 * 4 < total) {
        size_t idx = (size_t)i4 * 4;
        float4 vi = *(const float4*)(gi + idx);
        float4 vg = *(const float4*)(gg + idx);
        float4 vf = *(const float4*)(fc + idx);
        float4 vo = *(const float4*)(out + idx);
        float4 c = make_float4(vi.x * vg.x + vf.x, vi.y * vg.y + vf.y,
                               vi.z * vg.z + vf.z, vi.w * vg.w + vf.w);
        float4 h = make_float4(vo.x * tanhf(c.x), vo.y * tanhf(c.y),
                               vo.z * tanhf(c.z), vo.w * tanhf(c.w));
        *(float4*)(out + (size_t)total + idx) = c;
        *(float4*)(out + idx) = h;
    }
}

// ---------------------------------------------------------------------------
extern "C" void kernel_launch(void* const* d_in, const int* in_sizes, int n_in,
                              void* d_out, int out_size) {
    const float* child_hs = (const float*)d_in[0];
    const float* child_cs = (const float*)d_in[1];
    const int*   seg      = (const int*)d_in[2];
    const float* Wg = (const float*)d_in[4];
    const float* bg = (const float*)d_in[5];
    const float* Wf = (const float*)d_in[6];
    const float* bf = (const float*)d_in[7];
    (void)n_in;

    int E = in_sizes[2];
    int P = out_size / (2 * D);
    if (P > MAX_P) P = MAX_P;

    float* out = (float*)d_out;

    static bool inited = false;
    static float *fc_p, *ia_p, *ga_p, *hs_p, *wf_p, *wg_p;
    if (!inited) {
        cudaGetSymbolAddress((void**)&fc_p, g_fc);
        cudaGetSymbolAddress((void**)&ia_p, g_iact);
        cudaGetSymbolAddress((void**)&ga_p, g_gact);
        cudaGetSymbolAddress((void**)&hs_p, g_hs_sum);
        cudaGetSymbolAddress((void**)&wf_p, g_wf_t);
        cudaGetSymbolAddress((void**)&wg_p, g_wg_t);
        cudaFuncSetAttribute(k_gemm<0>, cudaFuncAttributeMaxDynamicSharedMemorySize, SM_TOTAL);
        cudaFuncSetAttribute(k_gemm<1>, cudaFuncAttributeMaxDynamicSharedMemorySize, SM_TOTAL);
        inited = true;
    }

    // weight transpose + tf32 rounding
    k_wsplit<<<dim3(D / 32, D / 32), 256>>>(Wf, D, wf_p);
    k_wsplit<<<dim3(D3 / 32, D / 32), 256>>>(Wg, D3, wg_p);

    // zero fc accumulator
    cudaMemsetAsync(fc_p, 0, (size_t)P * D * sizeof(float), 0);

    // segment sum of child_hs
    k_hs_sum<<<P, 256>>>(child_hs, seg, E, hs_p);

    // fGEMM: fc[seg[e]] += sigmoid(hs@Wf^T + bf) * cs
    k_gemm<0><<<dim3(2, (E + 127) / 128), 256, SM_TOTAL>>>(
        child_hs, wf_p, bf, child_cs, seg, fc_p,
        nullptr, nullptr, nullptr, E);

    // gates GEMM: gate 0 -> sig(i), 1 -> sig(o) into out_h, 2 -> tanh(g)
    k_gemm<1><<<dim3(6, (P + 127) / 128), 256, SM_TOTAL>>>(
        hs_p, wg_p, bg, nullptr, nullptr, nullptr,
        ia_p, out, ga_p, P);

    // final elementwise combine
    k_final<<<(P * D / 4 + 255) / 256, 256>>>(fc_p, ia_p, ga_p, out, P * D);
}